// round 7
// baseline (speedup 1.0000x reference)
#include <cuda_runtime.h>

#define NUM_BINS  512
#define NUM_NODES 128
#define N_PAIRS   1024
#define K_ELEMS   16384
#define NREP      32            // hist: one replica per lane -> conflict-free ATOMS
#define LREP      16            // lookup: 16 float2 replicas -> conflict-free LDS.64

#define TASKS_PER_PAIR 8
#define CHUNK_F4   512          // float4 per task (2048 elems)
#define TOTAL_TASKS (N_PAIRS * TASKS_PER_PAIR)   // 8192
#define HIST_BLOCKS   444       // 148 SMs * 3 CTAs (64KB smem) = one full wave
#define LOOKUP_BLOCKS 444       // 148 SMs * 3 CTAs (64KB smem) = one full wave

// Scratch (allocation-free rule: __device__ globals, zero-initialized at load)
__device__ float g_hist[NUM_NODES * NUM_BINS];
__device__ float g_tw[NUM_NODES];
__device__ float g_cdf[NUM_NODES * NUM_BINS];
// 2-byte lookup code per element: bin index if valid, 0xFFFF sentinel if not.
__device__ unsigned short g_code[(size_t)N_PAIRS * K_ELEMS];

// ---- packed f32x2 helpers (Blackwell; ptxas never auto-fuses these) --------
__device__ __forceinline__ unsigned long long pk2(float lo, float hi) {
    unsigned long long r;
    asm("mov.b64 %0, {%1, %2};" : "=l"(r) : "f"(lo), "f"(hi));
    return r;
}
__device__ __forceinline__ void upk2(unsigned long long v, float& lo, float& hi) {
    asm("mov.b64 {%0, %1}, %2;" : "=f"(lo), "=f"(hi) : "l"(v));
}
__device__ __forceinline__ unsigned long long mul2(unsigned long long a, unsigned long long b) {
    unsigned long long r;
    asm("mul.rn.f32x2 %0, %1, %2;" : "=l"(r) : "l"(a), "l"(b));
    return r;
}
__device__ __forceinline__ unsigned long long add2(unsigned long long a, unsigned long long b) {
    unsigned long long r;
    asm("add.rn.f32x2 %0, %1, %2;" : "=l"(r) : "l"(a), "l"(b));
    return r;
}

// ---------------------------------------------------------------------------
// Kernel 1: persistent hist (3 CTAs/SM). Lane-replicated smem histogram,
// flushed on pair change. Packed f32x2 arithmetic for bin/scale/wsum math.
// g_hist/g_tw are zero on entry (zeroed by cdf_kernel after use).
// ---------------------------------------------------------------------------
extern __shared__ float sh_dyn[];   // 64 KB, role depends on kernel

__global__ void __launch_bounds__(512, 3) hist_kernel(
    const float* __restrict__ res, const float* __restrict__ wgt,
    const int* __restrict__ src, const int* __restrict__ dst)
{
    float* sh_hist = sh_dyn;          // NUM_BINS * NREP floats
    __shared__ float sh_wsum;

    const int tid  = threadIdx.x;
    const int lane = tid & 31;

    const unsigned long long K512 = pk2(512.0f, 512.0f);
    const unsigned long long HALF = pk2(0.5f, 0.5f);

    int lo = (int)(((long long)blockIdx.x       * TOTAL_TASKS) / HIST_BLOCKS);
    int hi = (int)(((long long)(blockIdx.x + 1) * TOTAL_TASKS) / HIST_BLOCKS);

    int t = lo;
    while (t < hi) {
        const int p    = t / TASKS_PER_PAIR;
        const int tend = min(hi, (p + 1) * TASKS_PER_PAIR);

        // ---- zero the replicated histogram ----
        float4* shz = (float4*)sh_hist;
        #pragma unroll
        for (int i = 0; i < (NUM_BINS * NREP / 4) / 512; i++)
            shz[tid + i * 512] = make_float4(0.f, 0.f, 0.f, 0.f);
        if (tid == 0) sh_wsum = 0.0f;
        __syncthreads();

        const float4* r4 = (const float4*)(res + (size_t)p * K_ELEMS);
        const float4* w4 = (const float4*)(wgt + (size_t)p * K_ELEMS);
        ushort4* c4 = (ushort4*)(g_code + (size_t)p * K_ELEMS);

        const int i0 = (t    - p * TASKS_PER_PAIR) * CHUNK_F4;
        const int i1 = (tend - p * TASKS_PER_PAIR) * CHUNK_F4;

        unsigned long long wacc = 0ull;   // packed {0.0f, 0.0f}
        for (int i = i0 + tid; i < i1; i += 512) {
            float4 rv = __ldcs(&r4[i]);   // read-once: stream past L2
            float4 wv = __ldcs(&w4[i]);

            unsigned long long xp0 = mul2(pk2(rv.x, rv.y), K512);
            unsigned long long xp1 = mul2(pk2(rv.z, rv.w), K512);
            unsigned long long yp0 = add2(xp0, HALF);
            unsigned long long yp1 = add2(xp1, HALF);
            wacc = add2(wacc, pk2(wv.x, wv.y));
            wacc = add2(wacc, pk2(wv.z, wv.w));

            float xx[4], yy[4];
            upk2(xp0, xx[0], xx[1]); upk2(xp1, xx[2], xx[3]);
            upk2(yp0, yy[0], yy[1]); upk2(yp1, yy[2], yy[3]);
            float ww[4] = {wv.x, wv.y, wv.z, wv.w};

            unsigned short cc[4];
            #pragma unroll
            for (int j = 0; j < 4; j++) {
                int b = __float2int_rd(xx[j]);          // histogram bin
                if ((unsigned)b < NUM_BINS)
                    atomicAdd(&sh_hist[b * NREP + lane], ww[j]);  // bank==lane
                int b2 = __float2int_rd(yy[j]);          // lookup bin
                bool valid = ((unsigned)b2 < NUM_BINS) && (ww[j] > 0.0f);
                cc[j] = valid ? (unsigned short)b2 : (unsigned short)0xFFFFu;
            }
            c4[i] = make_ushort4(cc[0], cc[1], cc[2], cc[3]);
        }

        // fold packed accumulator, warp-reduce, one smem atomic per warp
        float wl, wh;
        upk2(wacc, wl, wh);
        float wsum = wl + wh;
        #pragma unroll
        for (int o = 16; o > 0; o >>= 1)
            wsum += __shfl_down_sync(0xffffffffu, wsum, o);
        if (lane == 0) atomicAdd(&sh_wsum, wsum);
        __syncthreads();

        // ---- reduce 32 copies -> 1 per bin, flush to global ----
        const int bin = tid;   // 512 threads == 512 bins
        float h = 0.0f;
        #pragma unroll
        for (int step = 0; step < NREP; step++)
            h += sh_hist[bin * NREP + ((lane + step) & 31)];   // conflict-free

        const int s = src[p];
        const int d = dst[p];
        atomicAdd(&g_hist[s * NUM_BINS + bin], h);
        atomicAdd(&g_hist[d * NUM_BINS + bin], h);
        if (tid == 0) {
            float ws = sh_wsum;
            atomicAdd(&g_tw[s], ws);
            atomicAdd(&g_tw[d], ws);
        }
        __syncthreads();   // protect smem before next segment's zeroing

        t = tend;
    }
}

// ---------------------------------------------------------------------------
// Kernel 2: cdf[node,:] = cumsum(hist[node,:] / (tw[node] + 1e-10)),
// then reset g_hist / g_tw to zero for the next invocation.
// ---------------------------------------------------------------------------
__global__ __launch_bounds__(512) void cdf_kernel() {
    __shared__ float warp_sums[16];

    const int node = blockIdx.x;
    const int tid  = threadIdx.x;

    const float inv_tw = 1.0f / (g_tw[node] + 1e-10f);
    float h = g_hist[node * NUM_BINS + tid];
    g_hist[node * NUM_BINS + tid] = 0.0f;     // reset for next call
    float x = h * inv_tw;

    #pragma unroll
    for (int o = 1; o < 32; o <<= 1) {
        float y = __shfl_up_sync(0xffffffffu, x, o);
        if ((tid & 31) >= o) x += y;
    }
    if ((tid & 31) == 31) warp_sums[tid >> 5] = x;
    __syncthreads();

    if (tid == 0) g_tw[node] = 0.0f;          // all reads of g_tw done pre-sync

    if (tid < 16) {
        float s = warp_sums[tid];
        #pragma unroll
        for (int o = 1; o < 16; o <<= 1) {
            float y = __shfl_up_sync(0x0000ffffu, s, o);
            if (tid >= o) s += y;
        }
        warp_sums[tid] = s;
    }
    __syncthreads();

    float base = (tid >= 32) ? warp_sums[(tid >> 5) - 1] : 0.0f;
    g_cdf[node * NUM_BINS + tid] = x + base;
}

// ---------------------------------------------------------------------------
// Kernel 3: persistent lookup. The pair's two cdf rows live interleaved as
// float2, replicated 16x: tab[c*16 + (lane&15)]. Within each half-warp phase
// of LDS.64 the lane&15 values are distinct -> conflict-free gather (2
// wavefronts per access, the HW minimum). Fill is staggered -> conflict-free.
// Output layout: out[0 : N*K) = src_cdf, out[N*K : 2*N*K) = dst_cdf.
// ---------------------------------------------------------------------------
__global__ void __launch_bounds__(512, 3) lookup_kernel(
    const int* __restrict__ src, const int* __restrict__ dst,
    float* __restrict__ out)
{
    float2* tab = (float2*)sh_dyn;    // NUM_BINS * LREP float2 = 64 KB

    const int tid    = threadIdx.x;
    const int lane16 = tid & 15;

    int lo = (int)(((long long)blockIdx.x       * TOTAL_TASKS) / LOOKUP_BLOCKS);
    int hi = (int)(((long long)(blockIdx.x + 1) * TOTAL_TASKS) / LOOKUP_BLOCKS);

    int t = lo;
    while (t < hi) {
        const int p    = t / TASKS_PER_PAIR;
        const int tend = min(hi, (p + 1) * TASKS_PER_PAIR);

        __syncthreads();   // previous segment's smem readers are done
        const int s = src[p];
        const int d = dst[p];
        {
            float2 v = make_float2(g_cdf[s * NUM_BINS + tid],
                                   g_cdf[d * NUM_BINS + tid]);
            #pragma unroll
            for (int r = 0; r < LREP; r++)          // stagger: conflict-free STS
                tab[tid * LREP + ((r + tid) & (LREP - 1))] = v;
        }
        __syncthreads();

        const ushort4* c4 = (const ushort4*)(g_code + (size_t)p * K_ELEMS);
        float4* o_s = (float4*)(out + (size_t)p * K_ELEMS);
        float4* o_d = (float4*)(out + (size_t)(N_PAIRS + p) * K_ELEMS);

        const int i0 = (t    - p * TASKS_PER_PAIR) * CHUNK_F4;
        const int i1 = (tend - p * TASKS_PER_PAIR) * CHUNK_F4;

        ushort4 cv = c4[i0 + tid];                  // depth-1 prefetch
        for (int i = i0 + tid; i < i1; i += 512) {
            ushort4 cn;
            if (i + 512 < i1) cn = c4[i + 512];
            unsigned short cc[4] = {cv.x, cv.y, cv.z, cv.w};
            float4 os, od;
            float* pos = (float*)&os;
            float* pod = (float*)&od;
            #pragma unroll
            for (int j = 0; j < 4; j++) {
                unsigned short c = cc[j];
                if (c < NUM_BINS) {
                    float2 v = tab[(int)c * LREP + lane16];   // LDS.64, no conflicts
                    pos[j] = v.x;
                    pod[j] = v.y;
                } else {
                    pos[j] = 2.0f;
                    pod[j] = 2.0f;
                }
            }
            __stcs(&o_s[i], os);   // streaming: never re-read
            __stcs(&o_d[i], od);
            cv = cn;
        }

        t = tend;
    }
}

// ---------------------------------------------------------------------------
extern "C" void kernel_launch(void* const* d_in, const int* in_sizes, int n_in,
                              void* d_out, int out_size)
{
    const float* res = (const float*)d_in[0];
    const float* wgt = (const float*)d_in[1];
    const int*   src = (const int*)d_in[2];
    const int*   dst = (const int*)d_in[3];
    float*       out = (float*)d_out;

    const int smem_h = NUM_BINS * NREP * sizeof(float);    // 64 KB
    const int smem_l = NUM_BINS * LREP * sizeof(float2);   // 64 KB
    cudaFuncSetAttribute(hist_kernel,
                         cudaFuncAttributeMaxDynamicSharedMemorySize, smem_h);
    cudaFuncSetAttribute(lookup_kernel,
                         cudaFuncAttributeMaxDynamicSharedMemorySize, smem_l);

    hist_kernel<<<HIST_BLOCKS, 512, smem_h>>>(res, wgt, src, dst);
    cdf_kernel<<<NUM_NODES, 512>>>();
    lookup_kernel<<<LOOKUP_BLOCKS, 512, smem_l>>>(src, dst, out);
}

// round 8
// speedup vs baseline: 1.0361x; 1.0361x over previous
#include <cuda_runtime.h>

#define NUM_BINS  512
#define NUM_NODES 128
#define N_PAIRS   1024
#define K_ELEMS   16384
#define NREP      16            // hist replicas: 32KB/CTA -> 4 CTAs/SM
#define LREP      16            // lookup: 16 float2 replicas -> conflict-free LDS.64

#define TASKS_PER_PAIR 8
#define CHUNK_F4   512          // float4 per task (2048 elems)
#define TOTAL_TASKS (N_PAIRS * TASKS_PER_PAIR)   // 8192
#define HIST_BLOCKS   592       // 148 SMs * 4 CTAs (32KB smem) = one full wave
#define LOOKUP_BLOCKS 444       // 148 SMs * 3 CTAs (64KB smem) = one full wave

// Scratch (allocation-free rule: __device__ globals, zero-initialized at load)
__device__ float g_hist[NUM_NODES * NUM_BINS];
__device__ float g_tw[NUM_NODES];
__device__ float g_cdf[NUM_NODES * NUM_BINS];
// 2-byte lookup code per element: bin index if valid, 0xFFFF sentinel if not.
__device__ unsigned short g_code[(size_t)N_PAIRS * K_ELEMS];

extern __shared__ float sh_dyn[];   // role depends on kernel

// ---------------------------------------------------------------------------
// Kernel 1: persistent hist, 4 CTAs/SM (32-reg cap, 32KB smem).
// 16-way lane-replicated smem histogram tab[bin*16 + (lane&15)].
// Zeroing is fused into the reduction (reducer writes zeros back), so each
// pair-segment costs one barrier pair and one 32KB read+write of smem.
// g_hist/g_tw are zero on entry (zeroed by cdf_kernel after use).
// ---------------------------------------------------------------------------
__global__ void __launch_bounds__(512, 4) hist_kernel(
    const float* __restrict__ res, const float* __restrict__ wgt,
    const int* __restrict__ src, const int* __restrict__ dst)
{
    float* tab = sh_dyn;              // NUM_BINS * NREP floats = 32 KB
    __shared__ float sh_wsum;

    const int tid    = threadIdx.x;
    const int lane   = tid & 31;
    const int lane16 = tid & 15;

    // one-time zero of the replicated histogram + wsum
    float4* shz = (float4*)tab;
    #pragma unroll
    for (int i = 0; i < (NUM_BINS * NREP / 4) / 512; i++)
        shz[tid + i * 512] = make_float4(0.f, 0.f, 0.f, 0.f);
    if (tid == 0) sh_wsum = 0.0f;
    __syncthreads();

    int lo = (int)(((long long)blockIdx.x       * TOTAL_TASKS) / HIST_BLOCKS);
    int hi = (int)(((long long)(blockIdx.x + 1) * TOTAL_TASKS) / HIST_BLOCKS);

    int t = lo;
    while (t < hi) {
        const int p    = t / TASKS_PER_PAIR;
        const int tend = min(hi, (p + 1) * TASKS_PER_PAIR);

        const float4* r4 = (const float4*)(res + (size_t)p * K_ELEMS);
        const float4* w4 = (const float4*)(wgt + (size_t)p * K_ELEMS);
        ushort4* c4 = (ushort4*)(g_code + (size_t)p * K_ELEMS);

        const int i0 = (t    - p * TASKS_PER_PAIR) * CHUNK_F4;
        const int i1 = (tend - p * TASKS_PER_PAIR) * CHUNK_F4;

        float wsum = 0.0f;
        for (int i = i0 + tid; i < i1; i += 512) {
            float4 rv = __ldcs(&r4[i]);   // read-once: stream past L2
            float4 wv = __ldcs(&w4[i]);
            float rr[4] = {rv.x, rv.y, rv.z, rv.w};
            float ww[4] = {wv.x, wv.y, wv.z, wv.w};
            unsigned short cc[4];
            #pragma unroll
            for (int j = 0; j < 4; j++) {
                wsum += ww[j];
                float x = rr[j] * 512.0f;          // *2^9 exact in fp32
                int b  = __float2int_rd(x);        // histogram bin
                if ((unsigned)b < NUM_BINS)
                    atomicAdd(&tab[b * NREP + lane16], ww[j]);
                int b2 = __float2int_rd(x + 0.5f); // lookup bin
                bool valid = ((unsigned)b2 < NUM_BINS) && (ww[j] > 0.0f);
                cc[j] = valid ? (unsigned short)b2 : (unsigned short)0xFFFFu;
            }
            c4[i] = make_ushort4(cc[0], cc[1], cc[2], cc[3]);
        }

        // warp-reduce wsum, one smem atomic per warp
        #pragma unroll
        for (int o = 16; o > 0; o >>= 1)
            wsum += __shfl_down_sync(0xffffffffu, wsum, o);
        if (lane == 0) atomicAdd(&sh_wsum, wsum);
        __syncthreads();

        // ---- reduce 16 replicas -> 1 per bin, zero slots behind the read.
        // r = ((lane>>1)+step)&15 makes every LDS/STS step conflict-free:
        // even lanes hit banks 0..15, odd lanes banks 16..31, all distinct.
        const int bin = tid;   // 512 threads == 512 bins
        float h = 0.0f;
        #pragma unroll
        for (int step = 0; step < NREP; step++) {
            int r = ((lane >> 1) + step) & (NREP - 1);
            h += tab[bin * NREP + r];
            tab[bin * NREP + r] = 0.0f;            // ready for next segment
        }

        const int s = src[p];
        const int d = dst[p];
        atomicAdd(&g_hist[s * NUM_BINS + bin], h);
        atomicAdd(&g_hist[d * NUM_BINS + bin], h);
        if (tid == 0) {
            float ws = sh_wsum;
            atomicAdd(&g_tw[s], ws);
            atomicAdd(&g_tw[d], ws);
            sh_wsum = 0.0f;        // same thread read it; reset before barrier
        }
        __syncthreads();           // next segment's atomics start after this

        t = tend;
    }
}

// ---------------------------------------------------------------------------
// Kernel 2: cdf[node,:] = cumsum(hist[node,:] / (tw[node] + 1e-10)),
// then reset g_hist / g_tw to zero for the next invocation.
// ---------------------------------------------------------------------------
__global__ __launch_bounds__(512) void cdf_kernel() {
    __shared__ float warp_sums[16];

    const int node = blockIdx.x;
    const int tid  = threadIdx.x;

    const float inv_tw = 1.0f / (g_tw[node] + 1e-10f);
    float h = g_hist[node * NUM_BINS + tid];
    g_hist[node * NUM_BINS + tid] = 0.0f;     // reset for next call
    float x = h * inv_tw;

    #pragma unroll
    for (int o = 1; o < 32; o <<= 1) {
        float y = __shfl_up_sync(0xffffffffu, x, o);
        if ((tid & 31) >= o) x += y;
    }
    if ((tid & 31) == 31) warp_sums[tid >> 5] = x;
    __syncthreads();

    if (tid == 0) g_tw[node] = 0.0f;          // all reads of g_tw done pre-sync

    if (tid < 16) {
        float s = warp_sums[tid];
        #pragma unroll
        for (int o = 1; o < 16; o <<= 1) {
            float y = __shfl_up_sync(0x0000ffffu, s, o);
            if (tid >= o) s += y;
        }
        warp_sums[tid] = s;
    }
    __syncthreads();

    float base = (tid >= 32) ? warp_sums[(tid >> 5) - 1] : 0.0f;
    g_cdf[node * NUM_BINS + tid] = x + base;
}

// ---------------------------------------------------------------------------
// Kernel 3: persistent lookup (at its HBM write floor; unchanged from R7).
// Interleaved float2 cdf table replicated 16x -> conflict-free LDS.64 gather.
// Output layout: out[0 : N*K) = src_cdf, out[N*K : 2*N*K) = dst_cdf.
// ---------------------------------------------------------------------------
__global__ void __launch_bounds__(512, 3) lookup_kernel(
    const int* __restrict__ src, const int* __restrict__ dst,
    float* __restrict__ out)
{
    float2* tab = (float2*)sh_dyn;    // NUM_BINS * LREP float2 = 64 KB

    const int tid    = threadIdx.x;
    const int lane16 = tid & 15;

    int lo = (int)(((long long)blockIdx.x       * TOTAL_TASKS) / LOOKUP_BLOCKS);
    int hi = (int)(((long long)(blockIdx.x + 1) * TOTAL_TASKS) / LOOKUP_BLOCKS);

    int t = lo;
    while (t < hi) {
        const int p    = t / TASKS_PER_PAIR;
        const int tend = min(hi, (p + 1) * TASKS_PER_PAIR);

        __syncthreads();   // previous segment's smem readers are done
        const int s = src[p];
        const int d = dst[p];
        {
            float2 v = make_float2(g_cdf[s * NUM_BINS + tid],
                                   g_cdf[d * NUM_BINS + tid]);
            #pragma unroll
            for (int r = 0; r < LREP; r++)          // stagger: conflict-free STS
                tab[tid * LREP + ((r + tid) & (LREP - 1))] = v;
        }
        __syncthreads();

        const ushort4* c4 = (const ushort4*)(g_code + (size_t)p * K_ELEMS);
        float4* o_s = (float4*)(out + (size_t)p * K_ELEMS);
        float4* o_d = (float4*)(out + (size_t)(N_PAIRS + p) * K_ELEMS);

        const int i0 = (t    - p * TASKS_PER_PAIR) * CHUNK_F4;
        const int i1 = (tend - p * TASKS_PER_PAIR) * CHUNK_F4;

        ushort4 cv = c4[i0 + tid];                  // depth-1 prefetch
        for (int i = i0 + tid; i < i1; i += 512) {
            ushort4 cn;
            if (i + 512 < i1) cn = c4[i + 512];
            unsigned short cc[4] = {cv.x, cv.y, cv.z, cv.w};
            float4 os, od;
            float* pos = (float*)&os;
            float* pod = (float*)&od;
            #pragma unroll
            for (int j = 0; j < 4; j++) {
                unsigned short c = cc[j];
                if (c < NUM_BINS) {
                    float2 v = tab[(int)c * LREP + lane16];   // conflict-free
                    pos[j] = v.x;
                    pod[j] = v.y;
                } else {
                    pos[j] = 2.0f;
                    pod[j] = 2.0f;
                }
            }
            __stcs(&o_s[i], os);   // streaming: never re-read
            __stcs(&o_d[i], od);
            cv = cn;
        }

        t = tend;
    }
}

// ---------------------------------------------------------------------------
extern "C" void kernel_launch(void* const* d_in, const int* in_sizes, int n_in,
                              void* d_out, int out_size)
{
    const float* res = (const float*)d_in[0];
    const float* wgt = (const float*)d_in[1];
    const int*   src = (const int*)d_in[2];
    const int*   dst = (const int*)d_in[3];
    float*       out = (float*)d_out;

    const int smem_h = NUM_BINS * NREP * sizeof(float);    // 32 KB
    const int smem_l = NUM_BINS * LREP * sizeof(float2);   // 64 KB
    cudaFuncSetAttribute(hist_kernel,
                         cudaFuncAttributeMaxDynamicSharedMemorySize, smem_h);
    cudaFuncSetAttribute(lookup_kernel,
                         cudaFuncAttributeMaxDynamicSharedMemorySize, smem_l);

    hist_kernel<<<HIST_BLOCKS, 512, smem_h>>>(res, wgt, src, dst);
    cdf_kernel<<<NUM_NODES, 512>>>();
    lookup_kernel<<<LOOKUP_BLOCKS, 512, smem_l>>>(src, dst, out);
}

// round 9
// speedup vs baseline: 1.0412x; 1.0049x over previous
#include <cuda_runtime.h>

#define NUM_BINS  512
#define NUM_NODES 128
#define N_PAIRS   1024
#define K_ELEMS   16384
#define NREP      16            // hist replicas: 32KB/CTA -> 4 CTAs/SM
#define LREP      16            // lookup: 16 float2 replicas -> conflict-free LDS.64

#define TASKS_PER_PAIR 8
#define CHUNK_F4   512          // float4 per task (2048 elems)
#define TOTAL_TASKS (N_PAIRS * TASKS_PER_PAIR)   // 8192
#define HIST_BLOCKS   592       // 148 SMs * 4 CTAs (32KB smem) = one full wave
#define LOOKUP_BLOCKS 444       // 148 SMs * 3 CTAs (64KB smem) = one full wave

// Scratch (allocation-free rule: __device__ globals, zero-initialized at load)
__device__ float g_hist[NUM_NODES * NUM_BINS];
__device__ float g_tw[NUM_NODES];
__device__ float g_cdf[NUM_NODES * NUM_BINS];
// 2-byte lookup code per element: bin index if valid, 0xFFFF sentinel if not.
__device__ unsigned short g_code[(size_t)N_PAIRS * K_ELEMS];

extern __shared__ float sh_dyn[];   // role depends on kernel

// ---------------------------------------------------------------------------
// Kernel 1: persistent hist, 4 CTAs/SM (32-reg cap, 32KB smem).
// 16-way replicated smem histogram tab[bin*16 + rep] with the half-warp-
// rotated replica index rep = (lane&15 + 8*(lane>>4)) & 15.
// Bank = 16*(bin&1) + rep: within a half-warp reps are distinct (no equal
// bank possible across the 16-offset), across half-warps equal banks would
// need equal bin parity AND rep equality, which the +8 rotation forbids.
// => ATOMS provably conflict-free at only 16 replicas.
// Zeroing fused into the reduction. g_hist/g_tw zero on entry.
// ---------------------------------------------------------------------------
__global__ void __launch_bounds__(512, 4) hist_kernel(
    const float* __restrict__ res, const float* __restrict__ wgt,
    const int* __restrict__ src, const int* __restrict__ dst)
{
    float* tab = sh_dyn;              // NUM_BINS * NREP floats = 32 KB
    __shared__ float sh_wsum;

    const int tid  = threadIdx.x;
    const int lane = tid & 31;
    const int rep  = (lane + ((lane >> 4) << 3)) & 15;   // rotated replica id

    // one-time zero of the replicated histogram + wsum
    float4* shz = (float4*)tab;
    #pragma unroll
    for (int i = 0; i < (NUM_BINS * NREP / 4) / 512; i++)
        shz[tid + i * 512] = make_float4(0.f, 0.f, 0.f, 0.f);
    if (tid == 0) sh_wsum = 0.0f;
    __syncthreads();

    int lo = (int)(((long long)blockIdx.x       * TOTAL_TASKS) / HIST_BLOCKS);
    int hi = (int)(((long long)(blockIdx.x + 1) * TOTAL_TASKS) / HIST_BLOCKS);

    int t = lo;
    while (t < hi) {
        const int p    = t / TASKS_PER_PAIR;
        const int tend = min(hi, (p + 1) * TASKS_PER_PAIR);

        const float4* r4 = (const float4*)(res + (size_t)p * K_ELEMS);
        const float4* w4 = (const float4*)(wgt + (size_t)p * K_ELEMS);
        ushort4* c4 = (ushort4*)(g_code + (size_t)p * K_ELEMS);

        const int i0 = (t    - p * TASKS_PER_PAIR) * CHUNK_F4;
        const int i1 = (tend - p * TASKS_PER_PAIR) * CHUNK_F4;

        float wsum = 0.0f;
        for (int i = i0 + tid; i < i1; i += 512) {
            float4 rv = __ldcs(&r4[i]);   // read-once: stream past L2
            float4 wv = __ldcs(&w4[i]);
            float rr[4] = {rv.x, rv.y, rv.z, rv.w};
            float ww[4] = {wv.x, wv.y, wv.z, wv.w};
            unsigned short cc[4];
            #pragma unroll
            for (int j = 0; j < 4; j++) {
                wsum += ww[j];
                float x = rr[j] * 512.0f;          // *2^9 exact in fp32
                int b  = __float2int_rd(x);        // histogram bin
                if ((unsigned)b < NUM_BINS)
                    atomicAdd(&tab[b * NREP + rep], ww[j]);   // conflict-free
                int b2 = __float2int_rd(x + 0.5f); // lookup bin
                bool valid = ((unsigned)b2 < NUM_BINS) && (ww[j] > 0.0f);
                cc[j] = valid ? (unsigned short)b2 : (unsigned short)0xFFFFu;
            }
            c4[i] = make_ushort4(cc[0], cc[1], cc[2], cc[3]);
        }

        // warp-reduce wsum, one smem atomic per warp
        #pragma unroll
        for (int o = 16; o > 0; o >>= 1)
            wsum += __shfl_down_sync(0xffffffffu, wsum, o);
        if (lane == 0) atomicAdd(&sh_wsum, wsum);
        __syncthreads();

        // ---- reduce 16 replicas -> 1 per bin, zero slots behind the read.
        // r = ((lane>>1)+step)&15: even lanes stay in banks 0..15, odd lanes
        // in banks 16..31, all distinct -> conflict-free LDS/STS.
        const int bin = tid;   // 512 threads == 512 bins
        float h = 0.0f;
        #pragma unroll
        for (int step = 0; step < NREP; step++) {
            int r = ((lane >> 1) + step) & (NREP - 1);
            h += tab[bin * NREP + r];
            tab[bin * NREP + r] = 0.0f;            // ready for next segment
        }

        const int s = src[p];
        const int d = dst[p];
        atomicAdd(&g_hist[s * NUM_BINS + bin], h);
        atomicAdd(&g_hist[d * NUM_BINS + bin], h);
        if (tid == 0) {
            float ws = sh_wsum;
            atomicAdd(&g_tw[s], ws);
            atomicAdd(&g_tw[d], ws);
            sh_wsum = 0.0f;        // same thread read it; reset before barrier
        }
        __syncthreads();           // next segment's atomics start after this

        t = tend;
    }
}

// ---------------------------------------------------------------------------
// Kernel 2: cdf[node,:] = cumsum(hist[node,:] / (tw[node] + 1e-10)),
// then reset g_hist / g_tw to zero for the next invocation.
// ---------------------------------------------------------------------------
__global__ __launch_bounds__(512) void cdf_kernel() {
    __shared__ float warp_sums[16];

    const int node = blockIdx.x;
    const int tid  = threadIdx.x;

    const float inv_tw = 1.0f / (g_tw[node] + 1e-10f);
    float h = g_hist[node * NUM_BINS + tid];
    g_hist[node * NUM_BINS + tid] = 0.0f;     // reset for next call
    float x = h * inv_tw;

    #pragma unroll
    for (int o = 1; o < 32; o <<= 1) {
        float y = __shfl_up_sync(0xffffffffu, x, o);
        if ((tid & 31) >= o) x += y;
    }
    if ((tid & 31) == 31) warp_sums[tid >> 5] = x;
    __syncthreads();

    if (tid == 0) g_tw[node] = 0.0f;          // all reads of g_tw done pre-sync

    if (tid < 16) {
        float s = warp_sums[tid];
        #pragma unroll
        for (int o = 1; o < 16; o <<= 1) {
            float y = __shfl_up_sync(0x0000ffffu, s, o);
            if (tid >= o) s += y;
        }
        warp_sums[tid] = s;
    }
    __syncthreads();

    float base = (tid >= 32) ? warp_sums[(tid >> 5) - 1] : 0.0f;
    g_cdf[node * NUM_BINS + tid] = x + base;
}

// ---------------------------------------------------------------------------
// Kernel 3: persistent lookup (at its HBM write floor).
// Interleaved float2 cdf table replicated 16x -> conflict-free LDS.64 gather.
// Output layout: out[0 : N*K) = src_cdf, out[N*K : 2*N*K) = dst_cdf.
// ---------------------------------------------------------------------------
__global__ void __launch_bounds__(512, 3) lookup_kernel(
    const int* __restrict__ src, const int* __restrict__ dst,
    float* __restrict__ out)
{
    float2* tab = (float2*)sh_dyn;    // NUM_BINS * LREP float2 = 64 KB

    const int tid    = threadIdx.x;
    const int lane16 = tid & 15;

    int lo = (int)(((long long)blockIdx.x       * TOTAL_TASKS) / LOOKUP_BLOCKS);
    int hi = (int)(((long long)(blockIdx.x + 1) * TOTAL_TASKS) / LOOKUP_BLOCKS);

    int t = lo;
    while (t < hi) {
        const int p    = t / TASKS_PER_PAIR;
        const int tend = min(hi, (p + 1) * TASKS_PER_PAIR);

        __syncthreads();   // previous segment's smem readers are done
        const int s = src[p];
        const int d = dst[p];
        {
            float2 v = make_float2(g_cdf[s * NUM_BINS + tid],
                                   g_cdf[d * NUM_BINS + tid]);
            #pragma unroll
            for (int r = 0; r < LREP; r++)          // stagger: conflict-free STS
                tab[tid * LREP + ((r + tid) & (LREP - 1))] = v;
        }
        __syncthreads();

        const ushort4* c4 = (const ushort4*)(g_code + (size_t)p * K_ELEMS);
        float4* o_s = (float4*)(out + (size_t)p * K_ELEMS);
        float4* o_d = (float4*)(out + (size_t)(N_PAIRS + p) * K_ELEMS);

        const int i0 = (t    - p * TASKS_PER_PAIR) * CHUNK_F4;
        const int i1 = (tend - p * TASKS_PER_PAIR) * CHUNK_F4;

        ushort4 cv = c4[i0 + tid];                  // depth-1 prefetch
        for (int i = i0 + tid; i < i1; i += 512) {
            ushort4 cn;
            if (i + 512 < i1) cn = c4[i + 512];
            unsigned short cc[4] = {cv.x, cv.y, cv.z, cv.w};
            float4 os, od;
            float* pos = (float*)&os;
            float* pod = (float*)&od;
            #pragma unroll
            for (int j = 0; j < 4; j++) {
                unsigned short c = cc[j];
                if (c < NUM_BINS) {
                    float2 v = tab[(int)c * LREP + lane16];   // conflict-free
                    pos[j] = v.x;
                    pod[j] = v.y;
                } else {
                    pos[j] = 2.0f;
                    pod[j] = 2.0f;
                }
            }
            __stcs(&o_s[i], os);   // streaming: never re-read
            __stcs(&o_d[i], od);
            cv = cn;
        }

        t = tend;
    }
}

// ---------------------------------------------------------------------------
extern "C" void kernel_launch(void* const* d_in, const int* in_sizes, int n_in,
                              void* d_out, int out_size)
{
    const float* res = (const float*)d_in[0];
    const float* wgt = (const float*)d_in[1];
    const int*   src = (const int*)d_in[2];
    const int*   dst = (const int*)d_in[3];
    float*       out = (float*)d_out;

    const int smem_h = NUM_BINS * NREP * sizeof(float);    // 32 KB
    const int smem_l = NUM_BINS * LREP * sizeof(float2);   // 64 KB
    cudaFuncSetAttribute(hist_kernel,
                         cudaFuncAttributeMaxDynamicSharedMemorySize, smem_h);
    cudaFuncSetAttribute(lookup_kernel,
                         cudaFuncAttributeMaxDynamicSharedMemorySize, smem_l);

    hist_kernel<<<HIST_BLOCKS, 512, smem_h>>>(res, wgt, src, dst);
    cdf_kernel<<<NUM_NODES, 512>>>();
    lookup_kernel<<<LOOKUP_BLOCKS, 512, smem_l>>>(src, dst, out);
}